// round 5
// baseline (speedup 1.0000x reference)
#include <cuda_runtime.h>

#define BN 8
#define HI 256
#define WI 256

__device__ float g_bufA[(size_t)BN * HI * WI * 64];
__device__ float g_bufB[(size_t)BN * HI * WI * 64];
__device__ float g_maskA[(size_t)BN * HI * WI];
__device__ float g_maskB[(size_t)BN * HI * WI];
__device__ float g_loss;

// gelu tanh-approx (jax approximate=True): 0.5x(1+tanh z) = x*sigmoid(2z)
__device__ __forceinline__ float gelu_f(float x) {
    float z2 = 1.5957691216057308f * (x + 0.044715f * x * x * x);
    float e = __expf(z2);
    return x * (1.0f - 1.0f / (e + 1.0f));
}

__global__ void zero_k() { g_loss = 0.0f; }
__global__ void fin_k(float* o) { o[0] = g_loss; }

// ---------- encoder stage 1: 3x3 conv 1->16 s1 SAME + chan-norm + gelu ----------
__global__ __launch_bounds__(128) void conv1_k(const float* __restrict__ img,
                                               const float* __restrict__ w,
                                               const float* __restrict__ bias,
                                               float* __restrict__ out) {
    __shared__ float ws[144];
    __shared__ float bs[16];
    for (int i = threadIdx.x; i < 144; i += 128) ws[i] = w[i];
    if (threadIdx.x < 16) bs[threadIdx.x] = bias[threadIdx.x];
    __syncthreads();

    int gid = blockIdx.x * 128 + threadIdx.x;   // BN*HI*WI threads exactly
    int b = gid >> 16;
    int oh = (gid >> 8) & 255;
    int ow = gid & 255;

    float acc[16];
#pragma unroll
    for (int c = 0; c < 16; c++) acc[c] = bs[c];
#pragma unroll
    for (int kh = 0; kh < 3; kh++) {
        int ih = oh + kh - 1;
        if (ih < 0 || ih >= HI) continue;
#pragma unroll
        for (int kw = 0; kw < 3; kw++) {
            int iw = ow + kw - 1;
            if (iw < 0 || iw >= WI) continue;
            float v = img[((size_t)(b * HI + ih) << 8) + iw];
            const float* wp = &ws[(kh * 3 + kw) * 16];
#pragma unroll
            for (int c = 0; c < 16; c++) acc[c] += v * wp[c];
        }
    }
    float mu = 0.f;
#pragma unroll
    for (int c = 0; c < 16; c++) mu += acc[c];
    mu *= (1.0f / 16.0f);
    float var = 0.f;
#pragma unroll
    for (int c = 0; c < 16; c++) { float d = acc[c] - mu; var += d * d; }
    var *= (1.0f / 16.0f);
    float rs = rsqrtf(var + 1e-6f);
    float* op = out + (size_t)gid * 16;
#pragma unroll
    for (int c = 0; c < 16; c++) op[c] = gelu_f((acc[c] - mu) * rs);
}

// ---------- stride-2 Conv_trio: 3x3 CIN->COUT s2 SAME (pad lo=0,hi=1) ----------
template <int CIN, int COUT>
__global__ __launch_bounds__(128) void trio_s2_k(const float* __restrict__ x,
                                                 float* __restrict__ out,
                                                 const float* __restrict__ w,
                                                 const float* __restrict__ bias,
                                                 int OH, int OW, int IH, int IW) {
    __shared__ float ws[3 * CIN * COUT];   // one kh slab [kw][ci][co]
    int gid = blockIdx.x * 128 + threadIdx.x;
    int total = BN * OH * OW;
    bool act = gid < total;
    int b = 0, oh = 0, ow = 0;
    if (act) {
        b = gid / (OH * OW);
        int r = gid - b * OH * OW;
        oh = r / OW;
        ow = r - oh * OW;
    }
    float acc[COUT];
#pragma unroll
    for (int c = 0; c < COUT; c++) acc[c] = 0.f;

    for (int kh = 0; kh < 3; kh++) {
        __syncthreads();
        for (int i = threadIdx.x; i < 3 * CIN * COUT; i += 128)
            ws[i] = w[kh * 3 * CIN * COUT + i];
        __syncthreads();
        if (!act) continue;
        int ih = oh * 2 + kh;
        if (ih >= IH) continue;
#pragma unroll
        for (int kw = 0; kw < 3; kw++) {
            int iw = ow * 2 + kw;
            if (iw >= IW) continue;
            const float4* xp = (const float4*)&x[(((size_t)b * IH + ih) * IW + iw) * CIN];
            const float* wp = &ws[kw * CIN * COUT];
#pragma unroll
            for (int c4 = 0; c4 < CIN / 4; c4++) {
                float4 xv = xp[c4];
                const float* w0 = &wp[(c4 * 4 + 0) * COUT];
                const float* w1 = &wp[(c4 * 4 + 1) * COUT];
                const float* w2 = &wp[(c4 * 4 + 2) * COUT];
                const float* w3 = &wp[(c4 * 4 + 3) * COUT];
#pragma unroll
                for (int c = 0; c < COUT; c++)
                    acc[c] += xv.x * w0[c] + xv.y * w1[c] + xv.z * w2[c] + xv.w * w3[c];
            }
        }
    }
    if (!act) return;
    float mu = 0.f;
#pragma unroll
    for (int c = 0; c < COUT; c++) { acc[c] += __ldg(&bias[c]); mu += acc[c]; }
    mu *= (1.0f / (float)COUT);
    float var = 0.f;
#pragma unroll
    for (int c = 0; c < COUT; c++) { float d = acc[c] - mu; var += d * d; }
    var *= (1.0f / (float)COUT);
    float rs = rsqrtf(var + 1e-6f);
    float* op = out + (size_t)gid * COUT;
#pragma unroll
    for (int c = 0; c < COUT; c++) op[c] = gelu_f((acc[c] - mu) * rs);
}

// ---------- conv_transpose 64->64, 3x3, stride 2 along DIM, + bias + gelu ----------
// JAX SAME deconv (k=3,s=2): pad_a=2,pad_b=1. Output v even: taps (cv=v/2-1,ks=0),
// (cv=v/2,ks=2); v odd: (cv=(v-1)/2,ks=1). Non-strided dim: standard pad 1.
// Block: 64 outputs along non-strided dim u x 64 co, fixed strided coord v.
template <int DIM>
__global__ __launch_bounds__(256) void deconv_k(const float* __restrict__ x,
                                                float* __restrict__ y,
                                                const float* __restrict__ w,
                                                const float* __restrict__ bias,
                                                int OH, int OW) {
    __shared__ float w_s[4096];       // one tap [ci][co]
    __shared__ float in_s[64 * 67];   // [ci][j], j covers u0-1..u0+64, pitch 67

    const int IH = (DIM == 0) ? OH / 2 : OH;
    const int IW = (DIM == 0) ? OW : OW / 2;
    const int U = (DIM == 0) ? OW : OH;
    const size_t su  = (DIM == 0) ? 64 : (size_t)IW * 64;   // input stride along u
    const size_t sv  = (DIM == 0) ? (size_t)IW * 64 : 64;   // input stride along strided dim
    const size_t sou = (DIM == 0) ? 64 : (size_t)OW * 64;
    const size_t sov = (DIM == 0) ? (size_t)OW * 64 : 64;

    const int t = threadIdx.x;
    const int u0 = blockIdx.x * 64;
    const int v = blockIdx.y;
    const int b = blockIdx.z;
    const float* xb = x + (size_t)b * IH * IW * 64;
    float* yb = y + (size_t)b * OH * OW * 64;
    const int co0 = (t & 15) * 4;
    const int px0 = (t >> 4) * 4;

    float4 acc[4];
#pragma unroll
    for (int p = 0; p < 4; p++) acc[p] = make_float4(0.f, 0.f, 0.f, 0.f);

    int scv[2], sks[2], ns = 0;
    if (v & 1) {
        scv[0] = v >> 1; sks[0] = 1; ns = 1;
    } else {
        if (v >= 2) { scv[0] = (v >> 1) - 1; sks[0] = 0; ns = 1; }
        scv[ns] = v >> 1; sks[ns] = 2; ns++;
    }

    for (int s = 0; s < ns; s++) {
        const int cv = scv[s];
        const int ks = sks[s];
        __syncthreads();
        for (int i = t; i < 66 * 64; i += 256) {
            int j = i >> 6, ci = i & 63;
            int iu = u0 - 1 + j;
            in_s[ci * 67 + j] = (iu >= 0 && iu < U)
                                    ? xb[(size_t)iu * su + (size_t)cv * sv + ci]
                                    : 0.f;
        }
        for (int kn = 0; kn < 3; kn++) {
            __syncthreads();
            {
                int tap = (DIM == 0) ? (ks * 3 + kn) : (kn * 3 + ks);
                const float4* sw = (const float4*)(w + (size_t)tap * 4096);
                float4* dw = (float4*)w_s;
                for (int i = t; i < 1024; i += 256) dw[i] = sw[i];
            }
            __syncthreads();
#pragma unroll 4
            for (int ci = 0; ci < 64; ci++) {
                float4 wv = *(const float4*)&w_s[ci * 64 + co0];
                const float* ip = &in_s[ci * 67 + px0 + kn];
                float a0 = ip[0], a1 = ip[1], a2 = ip[2], a3 = ip[3];
                acc[0].x += a0 * wv.x; acc[0].y += a0 * wv.y; acc[0].z += a0 * wv.z; acc[0].w += a0 * wv.w;
                acc[1].x += a1 * wv.x; acc[1].y += a1 * wv.y; acc[1].z += a1 * wv.z; acc[1].w += a1 * wv.w;
                acc[2].x += a2 * wv.x; acc[2].y += a2 * wv.y; acc[2].z += a2 * wv.z; acc[2].w += a2 * wv.w;
                acc[3].x += a3 * wv.x; acc[3].y += a3 * wv.y; acc[3].z += a3 * wv.z; acc[3].w += a3 * wv.w;
            }
        }
    }

    float4 bv = *(const float4*)&bias[co0];
#pragma unroll
    for (int p = 0; p < 4; p++) {
        int u = u0 + px0 + p;
        if (u >= U) continue;
        float4 o;
        o.x = gelu_f(acc[p].x + bv.x);
        o.y = gelu_f(acc[p].y + bv.y);
        o.z = gelu_f(acc[p].z + bv.z);
        o.w = gelu_f(acc[p].w + bv.w);
        *(float4*)&yb[(size_t)u * sou + (size_t)v * sov + co0] = o;
    }
}

// ---------- mask head: 3x3 conv 64->4 + softmax + mask update + loss ----------
__global__ __launch_bounds__(256) void mask_loss_k(const float* __restrict__ y,
                                                   const float* __restrict__ mw,
                                                   const float* __restrict__ mb,
                                                   const float* __restrict__ image,
                                                   const float* __restrict__ min_,
                                                   float* __restrict__ mout,
                                                   int hh, int ww, int dim,
                                                   int fh, int fw, float lw) {
    __shared__ float4 ws4[576];   // [tap*64+ci] -> weights for 4 outputs
    __shared__ float red[256];
    for (int i = threadIdx.x; i < 576; i += 256) ws4[i] = ((const float4*)mw)[i];
    __syncthreads();

    int gid = blockIdx.x * 256 + threadIdx.x;
    int total = BN * hh * ww;
    float local = 0.f;

    if (gid < total) {
        int b = gid / (hh * ww);
        int r = gid - b * hh * ww;
        int oh = r / ww;
        int ow = r - oh * ww;

        float4 m = *(const float4*)mb;
#pragma unroll
        for (int kh = 0; kh < 3; kh++) {
            int ph = oh + kh - 1;
            if (ph < 0 || ph >= hh) continue;
#pragma unroll
            for (int kw = 0; kw < 3; kw++) {
                int pw = ow + kw - 1;
                if (pw < 0 || pw >= ww) continue;
                const float4* a = (const float4*)&y[(((size_t)b * hh + ph) * ww + pw) * 64];
                const float4* wp = &ws4[(kh * 3 + kw) * 64];
#pragma unroll
                for (int c4 = 0; c4 < 16; c4++) {
                    float4 av = a[c4];
                    float4 w0 = wp[c4 * 4 + 0];
                    m.x += av.x * w0.x; m.y += av.x * w0.y; m.z += av.x * w0.z; m.w += av.x * w0.w;
                    float4 w1 = wp[c4 * 4 + 1];
                    m.x += av.y * w1.x; m.y += av.y * w1.y; m.z += av.y * w1.z; m.w += av.y * w1.w;
                    float4 w2 = wp[c4 * 4 + 2];
                    m.x += av.z * w2.x; m.y += av.z * w2.y; m.z += av.z * w2.z; m.w += av.z * w2.w;
                    float4 w3 = wp[c4 * 4 + 3];
                    m.x += av.w * w3.x; m.y += av.w * w3.y; m.z += av.w * w3.z; m.w += av.w * w3.w;
                }
            }
        }
        // softmax over 4
        float mx = fmaxf(fmaxf(m.x, m.y), fmaxf(m.z, m.w));
        float e0 = __expf(m.x - mx), e1 = __expf(m.y - mx);
        float e2 = __expf(m.z - mx), e3 = __expf(m.w - mx);
        float inv = 1.0f / (e0 + e1 + e2 + e3);
        float p0 = e0 * inv, p1 = e1 * inv, p2 = e2 * inv, p3 = e3 * inv;
        float sprob = p1 + 2.0f * p2 + 3.0f * p3;
        float ent = -(p0 * __logf(p0 + 1e-8f) + p1 * __logf(p1 + 1e-8f) +
                      p2 * __logf(p2 + 1e-8f) + p3 * __logf(p3 + 1e-8f));
        // downsampled image
        float sum = 0.f;
        for (int u = 0; u < fh; u++)
            for (int vv = 0; vv < fw; vv++)
                sum += image[((size_t)(b * HI + oh * fh + u)) * WI + ow * fw + vv];
        float ds = sum / (float)(fh * fw);
        float d = sprob * (1.0f / 3.0f) - ds;
        local = lw * (ent + d * d) / (float)total;
        // masks = repeat(prev, 2, axis=dim+1) + 0.25 * sprob
        int ph2 = (dim == 0) ? (hh >> 1) : hh;
        int pw2 = (dim == 1) ? (ww >> 1) : ww;
        int moh = (dim == 0) ? (oh >> 1) : oh;
        int mow = (dim == 1) ? (ow >> 1) : ow;
        mout[gid] = min_[((size_t)b * ph2 + moh) * pw2 + mow] + 0.25f * sprob;
    }

    red[threadIdx.x] = local;
    __syncthreads();
    for (int st = 128; st > 0; st >>= 1) {
        if (threadIdx.x < st) red[threadIdx.x] += red[threadIdx.x + st];
        __syncthreads();
    }
    if (threadIdx.x == 0) atomicAdd(&g_loss, red[0]);
}

// ---------------------------------------------------------------------------
extern "C" void kernel_launch(void* const* d_in, const int* in_sizes, int n_in,
                              void* d_out, int out_size) {
    const float* image  = (const float*)d_in[0];
    // d_in[1] = dynamic_cfg (unused)
    const float* w1 = (const float*)d_in[2];
    const float* b1 = (const float*)d_in[3];
    const float* w2 = (const float*)d_in[4];
    const float* b2 = (const float*)d_in[5];
    const float* w3 = (const float*)d_in[6];
    const float* b3 = (const float*)d_in[7];
    const float* w4 = (const float*)d_in[8];
    const float* b4 = (const float*)d_in[9];
    const float* up_w = (const float*)d_in[10];
    const float* up_b = (const float*)d_in[11];
    const float* mask_w = (const float*)d_in[12];
    const float* mask_b = (const float*)d_in[13];
    const float* masks0 = (const float*)d_in[14];
    float* out = (float*)d_out;

    float *bufA, *bufB, *maskA, *maskB;
    cudaGetSymbolAddress((void**)&bufA, g_bufA);
    cudaGetSymbolAddress((void**)&bufB, g_bufB);
    cudaGetSymbolAddress((void**)&maskA, g_maskA);
    cudaGetSymbolAddress((void**)&maskB, g_maskB);

    zero_k<<<1, 1>>>();

    // encoder
    conv1_k<<<(BN * HI * WI) / 128, 128>>>(image, w1, b1, bufA);
    trio_s2_k<16, 16><<<(BN * 128 * 128) / 128, 128>>>(bufA, bufB, w2, b2, 128, 128, 256, 256);
    trio_s2_k<16, 32><<<(BN * 64 * 64) / 128, 128>>>(bufB, bufA, w3, b3, 64, 64, 128, 128);
    trio_s2_k<32, 64><<<(BN * 32 * 32) / 128, 128>>>(bufA, bufB, w4, b4, 32, 32, 64, 64);

    float* cur = bufB;
    float* nxt = bufA;
    const float* mcur = masks0;
    int h = 32, w = 32;
    const float LW[6] = {0.1f, 0.1f, 0.5f, 0.5f, 1.0f, 1.0f};

    for (int i = 0; i < 6; i++) {
        int dim = i % 2;
        if (dim == 0) h *= 2; else w *= 2;
        int U = (dim == 0) ? w : h;
        int V = (dim == 0) ? h : w;
        dim3 grid((U + 63) / 64, V, BN);
        if (dim == 0)
            deconv_k<0><<<grid, 256>>>(cur, nxt, up_w, up_b, h, w);
        else
            deconv_k<1><<<grid, 256>>>(cur, nxt, up_w, up_b, h, w);
        float* tmp = cur; cur = nxt; nxt = tmp;

        float* mout = (i == 5) ? (out + 1) : ((i % 2 == 0) ? maskA : maskB);
        int total = BN * h * w;
        mask_loss_k<<<(total + 255) / 256, 256>>>(cur, mask_w, mask_b, image, mcur,
                                                  mout, h, w, dim, HI / h, WI / w, LW[i]);
        mcur = mout;
    }

    fin_k<<<1, 1>>>(out);
}